// round 14
// baseline (speedup 1.0000x reference)
#include <cuda_runtime.h>
#include <cuda_fp16.h>
#include <math.h>
#include <stdint.h>

#define HID    1024
#define INP    512
#define BATCH  64
#define TT     512
#define RGRID  128
#define NTHR   512

// recurrence smem: per-warp private A regions + reduction buffer
#define AW_STR   40                         // halves per row (32 + 8 pad; 16B-aligned rows)
#define AW_CC_B  (32 * AW_STR * 2)          // one warp-chunk region: 2560 B
#define AW_W_B   (4 * AW_CC_B)              // per warp (4 chunks): 10240 B
#define A_TOT_B  (16 * AW_W_B)              // 163840 B
#define RED_B    (16 * 6 * 128 * 4)         // 49152 B
#define RSMEM_BYTES (A_TOT_B + RED_B)

// igemm smem (fused 3-gate): xs[2][128*IG_STR] + ws[2][3][64*IG_STR] halves
#define IG_STR 40
#define IGS_X  (128 * IG_STR)
#define IGS_W  (64 * IG_STR)
#define IGSM_BYTES ((2 * IGS_X + 6 * IGS_W) * 2)

// Scratch (device globals — allocation-free contract)
__device__ float  g_xg[(size_t)3 * TT * BATCH * HID];  // [g][t][b][h] input projections
__device__ __half g_xh[(size_t)BATCH * TT * INP];      // fp16 copy of x
__device__ __half g_wih[3][HID * INP];                 // fp16 copies of W_i_{r,z,n}
__device__ __half g_h[BATCH * HID];                    // hidden state (fp16)
__device__ unsigned g_count;                           // global barrier counter

// ---------------------------------------------------------------------------
__device__ __forceinline__ void mma_f16(float c[4], uint32_t a0, uint32_t a1,
                                        uint32_t a2, uint32_t a3,
                                        uint32_t b0, uint32_t b1) {
    asm volatile(
        "mma.sync.aligned.m16n8k16.row.col.f32.f16.f16.f32 "
        "{%0,%1,%2,%3}, {%4,%5,%6,%7}, {%8,%9}, {%0,%1,%2,%3};\n"
        : "+f"(c[0]), "+f"(c[1]), "+f"(c[2]), "+f"(c[3])
        : "r"(a0), "r"(a1), "r"(a2), "r"(a3), "r"(b0), "r"(b1));
}

__device__ __forceinline__ void ldsm_x4(uint32_t& r0, uint32_t& r1,
                                        uint32_t& r2, uint32_t& r3, uint32_t addr) {
    asm volatile("ldmatrix.sync.aligned.m8n8.x4.shared.b16 {%0,%1,%2,%3}, [%4];"
                 : "=r"(r0), "=r"(r1), "=r"(r2), "=r"(r3) : "r"(addr));
}

__device__ __forceinline__ void cp16ca(void* dst, const void* src) {
    uint32_t d = (uint32_t)__cvta_generic_to_shared(dst);
    asm volatile("cp.async.ca.shared.global [%0], [%1], 16;\n" :: "r"(d), "l"(src));
}
__device__ __forceinline__ void cp16cg(void* dst, const void* src) {
    uint32_t d = (uint32_t)__cvta_generic_to_shared(dst);
    asm volatile("cp.async.cg.shared.global [%0], [%1], 16;\n" :: "r"(d), "l"(src));
}
__device__ __forceinline__ void cp_commit() { asm volatile("cp.async.commit_group;\n"); }

__device__ __forceinline__ float sigmoidf_fast(float x) {
    return 1.0f / (1.0f + __expf(-x));
}
__device__ __forceinline__ float tanhf_fast(float x) {
    return 2.0f / (1.0f + __expf(-2.0f * x)) - 1.0f;
}

// ---------------------------------------------------------------------------
__global__ void reset_kernel()
{
    int i = blockIdx.x * blockDim.x + threadIdx.x;
    if (i == 0) g_count = 0u;
    if (i < BATCH * HID) g_h[i] = __float2half(0.0f);
}

// ---------------------------------------------------------------------------
// Convert x and W_i_* to fp16 (one-time pre-pass).
__global__ __launch_bounds__(256) void convert_kernel(
    const float* __restrict__ x,
    const float* __restrict__ Wr, const float* __restrict__ Wz, const float* __restrict__ Wn)
{
    const size_t stride = (size_t)gridDim.x * blockDim.x;
    const size_t i0 = (size_t)blockIdx.x * blockDim.x + threadIdx.x;

    const size_t NX4 = (size_t)BATCH * TT * INP / 4;
    for (size_t j = i0; j < NX4; j += stride) {
        float4 v = ((const float4*)x)[j];
        ((__half2*)g_xh)[j * 2]     = __floats2half2_rn(v.x, v.y);
        ((__half2*)g_xh)[j * 2 + 1] = __floats2half2_rn(v.z, v.w);
    }
    const size_t NW4 = (size_t)HID * INP / 4;
    for (size_t j = i0; j < NW4; j += stride) {
        float4 a = ((const float4*)Wr)[j];
        float4 b = ((const float4*)Wz)[j];
        float4 c = ((const float4*)Wn)[j];
        ((__half2*)g_wih[0])[j * 2]     = __floats2half2_rn(a.x, a.y);
        ((__half2*)g_wih[0])[j * 2 + 1] = __floats2half2_rn(a.z, a.w);
        ((__half2*)g_wih[1])[j * 2]     = __floats2half2_rn(b.x, b.y);
        ((__half2*)g_wih[1])[j * 2 + 1] = __floats2half2_rn(b.z, b.w);
        ((__half2*)g_wih[2])[j * 2]     = __floats2half2_rn(c.x, c.y);
        ((__half2*)g_wih[2])[j * 2 + 1] = __floats2half2_rn(c.z, c.w);
    }
}

// ---------------------------------------------------------------------------
// Input projection GEMM, fused over the 3 gates (fp16 MMA m16n8k16) — R12.
__global__ __launch_bounds__(256) void igemm_f16_fused(
    const float* __restrict__ br, const float* __restrict__ bz, const float* __restrict__ bn)
{
    extern __shared__ __half igs[];
    __half* xs = igs;                  // [2][IGS_X]
    __half* ws = igs + 2 * IGS_X;      // [2][3][IGS_W]

    const int m0 = blockIdx.y * 128;
    const int n0 = blockIdx.x * 64;
    const int tid  = threadIdx.x;
    const int w    = tid >> 5;
    const int lane = tid & 31;
    const int ar   = lane >> 2;
    const int ac   = lane & 3;
    const int wm   = w >> 1;
    const int wn   = w & 1;

    float acc[3][2][4][4];
#pragma unroll
    for (int g = 0; g < 3; g++)
#pragma unroll
        for (int mt = 0; mt < 2; mt++)
#pragma unroll
            for (int nt = 0; nt < 4; nt++)
#pragma unroll
                for (int q = 0; q < 4; q++) acc[g][mt][nt][q] = 0.0f;

    auto load_chunk = [&](int c) {
        const int k0 = c * 32;
        __half* xd = xs + (c & 1) * IGS_X;
        {
            int i = tid;
            int r = i >> 2, q = i & 3;
            cp16ca(&xd[r * IG_STR + q * 8], &g_xh[(size_t)(m0 + r) * INP + k0 + q * 8]);
            i = tid + 256; r = i >> 2; q = i & 3;
            cp16ca(&xd[r * IG_STR + q * 8], &g_xh[(size_t)(m0 + r) * INP + k0 + q * 8]);
        }
        __half* wd = ws + (c & 1) * (3 * IGS_W);
#pragma unroll
        for (int rep = 0; rep < 3; rep++) {
            const int job = tid + rep * 256;
            const int g  = job >> 8;
            const int rr = (job & 255) >> 2;
            const int q  = job & 3;
            cp16ca(&wd[g * IGS_W + rr * IG_STR + q * 8],
                   &g_wih[g][(size_t)(n0 + rr) * INP + k0 + q * 8]);
        }
        cp_commit();
    };

    load_chunk(0);

    for (int c = 0; c < INP / 32; c++) {
        asm volatile("cp.async.wait_group 0;\n");
        __syncthreads();
        if (c + 1 < INP / 32) load_chunk(c + 1);

        const __half* xb = xs + (c & 1) * IGS_X;
        const __half* wb = ws + (c & 1) * (3 * IGS_W);
        const uint32_t xb_base = (uint32_t)__cvta_generic_to_shared(xb);
        const uint32_t rowoff_b = 2u * ((uint32_t)(lane & 15) * IG_STR + (uint32_t)(lane >> 4) * 8);

#pragma unroll
        for (int s2 = 0; s2 < 2; s2++) {
            uint32_t afr[2][4];
#pragma unroll
            for (int mt = 0; mt < 2; mt++) {
                const uint32_t addr = xb_base
                    + 2u * (uint32_t)((wm * 32 + mt * 16) * IG_STR + s2 * 16)
                    + rowoff_b;
                ldsm_x4(afr[mt][0], afr[mt][1], afr[mt][2], afr[mt][3], addr);
            }
#pragma unroll
            for (int g = 0; g < 3; g++) {
#pragma unroll
                for (int nt = 0; nt < 4; nt++) {
                    const __half* bp = &wb[g * IGS_W
                        + (wn * 32 + nt * 8 + ar) * IG_STR + s2 * 16 + 2 * ac];
                    const uint32_t b0 = *(const uint32_t*)bp;
                    const uint32_t b1 = *(const uint32_t*)(bp + 8);
#pragma unroll
                    for (int mt = 0; mt < 2; mt++)
                        mma_f16(acc[g][mt][nt], afr[mt][0], afr[mt][1], afr[mt][2], afr[mt][3],
                                b0, b1);
                }
            }
        }
        __syncthreads();
    }

#pragma unroll
    for (int g = 0; g < 3; g++) {
        const float* __restrict__ bias = (g == 0) ? br : ((g == 1) ? bz : bn);
#pragma unroll
        for (int mt = 0; mt < 2; mt++) {
#pragma unroll
            for (int nt = 0; nt < 4; nt++) {
                const int h   = n0 + wn * 32 + nt * 8 + ac * 2;
                const float bv0 = bias[h], bv1 = bias[h + 1];

                int row = m0 + wm * 32 + mt * 16 + ar;
                int b = row >> 9, t = row & (TT - 1);
                size_t base = (((size_t)g * TT + t) * BATCH + b) * HID + h;
                *(float2*)&g_xg[base] = make_float2(acc[g][mt][nt][0] + bv0,
                                                    acc[g][mt][nt][1] + bv1);

                row += 8;
                b = row >> 9; t = row & (TT - 1);
                base = (((size_t)g * TT + t) * BATCH + b) * HID + h;
                *(float2*)&g_xg[base] = make_float2(acc[g][mt][nt][2] + bv0,
                                                    acc[g][mt][nt][3] + bv1);
            }
        }
    }
}

// ---------------------------------------------------------------------------
// Persistent recurrence kernel — 512 threads (16 warps), warp-autonomous
// phase A. Warp (mh = w>>3, kq = w&7) owns batches [mh*32,+32) x k-cols
// [kq*32,+32) of each 256-chunk. Private smem regions, per-warp cp groups,
// zero block syncs in phase A. Chunk order rotated by bid&3. One global
// barrier per step; out-stores and x(t+1) prefetch overlap the barrier wait.
__global__ __launch_bounds__(NTHR, 1) void recur_kernel(
    const float* __restrict__ Wr, const float* __restrict__ Wz, const float* __restrict__ Wn,
    const float* __restrict__ bhr, const float* __restrict__ bhz, const float* __restrict__ bhn,
    float* __restrict__ out)
{
    extern __shared__ char smc[];
    __half* As  = (__half*)smc;                 // [16 warps][4 cc][32 rows][AW_STR]
    float*  red = (float*)(smc + A_TOT_B);      // [16][6][128]

    const int tid  = threadIdx.x;
    const int bid  = blockIdx.x;
    const int w    = tid >> 5;
    const int lane = tid & 31;
    const int ar   = lane >> 2;
    const int ac   = lane & 3;
    const int H0   = bid * 8;
    const int mh   = w >> 3;         // m-half (0..1)
    const int kq   = w & 7;          // k-eighth (0..7)
    const int rot  = bid & 3;        // chunk rotation

    // epilogue mapping: one output per thread: col ec (0..7), batch m0 (0..63)
    const int ec = tid & 7;
    const int m0 = tid >> 3;
    const int hcol = H0 + ec;
    const float bR = __ldg(&bhr[hcol]);
    const float bZ = __ldg(&bhz[hcol]);
    const float bN = __ldg(&bhn[hcol]);

    // epilogue red-read offset
    const int mh2   = m0 >> 5;             // which warp group
    const int mrow  = m0 & 31;
    const int emt2  = mrow >> 4;
    const int mloc  = mrow & 15;
    const int rem   = ((((mloc & 7) << 2) | ((ec >> 1) & 3)) << 2)
                    | (((mloc >> 3) << 1) | (ec & 1));

    // ---- W fragments into registers; slot cc holds k-range ((rot+cc)&3)*256 ----
    uint32_t wreg[4][2][3][2];
#pragma unroll
    for (int cc = 0; cc < 4; cc++) {
        const int kbase = ((rot + cc) & 3) * 256;
#pragma unroll
        for (int s2 = 0; s2 < 2; s2++)
#pragma unroll
            for (int nt = 0; nt < 3; nt++) {
                const float* __restrict__ Wp = (nt == 0) ? Wr : ((nt == 1) ? Wz : Wn);
                const float* rowp = &Wp[(size_t)(H0 + ar) * HID];
#pragma unroll
                for (int q = 0; q < 2; q++) {
                    const int k = kbase + kq * 32 + s2 * 16 + q * 8 + 2 * ac;
                    float2 v = *(const float2*)&rowp[k];
                    __half2 h2 = __floats2half2_rn(v.x, v.y);
                    wreg[cc][s2][nt][q] = *(uint32_t*)&h2;
                }
            }
    }

    const uint32_t as_base = (uint32_t)__cvta_generic_to_shared(As);
    const uint32_t wbase_b = (uint32_t)w * AW_W_B;
    const uint32_t rowoff_b = 2u * ((uint32_t)(lane & 15) * AW_STR + (uint32_t)(lane >> 4) * 8);

    // per-warp load of chunk slot cc: 32 rows x 32 k; 8 rows x 64B per iter
    const int lrow = lane >> 2;      // 0..7
    const int lpc  = lane & 3;       // 0..3 (16B piece within 64B row-seg)
    auto load_chunk = [&](int cc, int kbase) {
        __half* dst = As + ((size_t)w * 4 + cc) * (32 * AW_STR);
        const int ksrc = kbase + kq * 32 + lpc * 8;
#pragma unroll
        for (int it = 0; it < 4; it++) {
            const int row = it * 8 + lrow;               // 0..31 within half
            cp16cg(&dst[row * AW_STR + lpc * 8],
                   &g_h[(size_t)(mh * 32 + row) * HID + ksrc]);
        }
        cp_commit();
    };

    const int kof[4] = { ((rot + 0) & 3) * 256, ((rot + 1) & 3) * 256,
                         ((rot + 2) & 3) * 256, ((rot + 3) & 3) * 256 };

    // epilogue x operands: prefetch t = 0
    const size_t SL = (size_t)TT * BATCH * HID;
    const size_t xb0 = (size_t)m0 * HID + hcol;
    float xr0 = __ldg(&g_xg[xb0]);
    float xz0 = __ldg(&g_xg[SL + xb0]);
    float xn0 = __ldg(&g_xg[2 * SL + xb0]);
    float hv0 = 0.0f;                // h(0) == 0

    unsigned phase = 0;

    for (int t = 0; t < TT; t++) {
        // issue this warp's 4 chunk loads (4 per-thread commit groups)
        load_chunk(0, kof[0]); load_chunk(1, kof[1]);
        load_chunk(2, kof[2]); load_chunk(3, kof[3]);

        float acc[2][3][4];
#pragma unroll
        for (int mt2 = 0; mt2 < 2; mt2++)
#pragma unroll
            for (int nt = 0; nt < 3; nt++)
#pragma unroll
                for (int q = 0; q < 4; q++) acc[mt2][nt][q] = 0.0f;

        // warp-autonomous compute: no block syncs
#pragma unroll
        for (int cc = 0; cc < 4; cc++) {
            if (cc == 0)      asm volatile("cp.async.wait_group 3;\n");
            else if (cc == 1) asm volatile("cp.async.wait_group 2;\n");
            else if (cc == 2) asm volatile("cp.async.wait_group 1;\n");
            else              asm volatile("cp.async.wait_group 0;\n");
            __syncwarp();

            const uint32_t buf = as_base + wbase_b + (uint32_t)cc * AW_CC_B;
#pragma unroll
            for (int s2 = 0; s2 < 2; s2++) {
                const uint32_t kb_b = 2u * (uint32_t)(s2 * 16);
#pragma unroll
                for (int mt2 = 0; mt2 < 2; mt2++) {
                    uint32_t a0, a1, a2, a3;
                    const uint32_t addr = buf + 2u * (uint32_t)(mt2 * 16 * AW_STR)
                                        + kb_b + rowoff_b;
                    ldsm_x4(a0, a1, a2, a3, addr);
#pragma unroll
                    for (int nt = 0; nt < 3; nt++)
                        mma_f16(acc[mt2][nt], a0, a1, a2, a3,
                                wreg[cc][s2][nt][0], wreg[cc][s2][nt][1]);
                }
            }
        }

        // ---- write per-warp partials ----
#pragma unroll
        for (int mt2 = 0; mt2 < 2; mt2++)
#pragma unroll
            for (int nt = 0; nt < 3; nt++) {
                const int tile = mt2 * 3 + nt;
                *(float4*)&red[((w * 6 + tile) * 128) + lane * 4] =
                    make_float4(acc[mt2][nt][0], acc[mt2][nt][1],
                                acc[mt2][nt][2], acc[mt2][nt][3]);
            }
        __syncthreads();

        // ---- fused reduction + gate epilogue (one output per thread) ----
        float h0;
        {
            float A0[3];
#pragma unroll
            for (int nt = 0; nt < 3; nt++) {
                const int tile = emt2 * 3 + nt;
                float s = 0.0f;
#pragma unroll
                for (int k2 = 0; k2 < 8; k2++)
                    s += red[(((mh2 * 8 + k2) * 6 + tile) * 128) + rem];
                A0[nt] = s;
            }

            const float r0 = sigmoidf_fast(xr0 + A0[0] + bR);
            const float z0 = sigmoidf_fast(xz0 + A0[1] + bZ);
            const float n0 = tanhf_fast(xn0 + r0 * (A0[2] + bN));
            h0 = (1.0f - z0) * n0 + z0 * hv0;
            const __half h0h = __float2half(h0);
            g_h[(size_t)m0 * HID + hcol] = h0h;
            hv0 = __half2float(h0h);
        }

        // ---- barrier: arrive, then overlap out-store + x(t+1) prefetch ----
        phase += 1;
        const unsigned target = phase * RGRID;
        __syncthreads();                  // all g_h stores issued block-wide
        if (tid == 0) {
            unsigned old;
            asm volatile("atom.add.release.gpu.u32 %0, [%1], 1;"
                         : "=r"(old) : "l"(&g_count) : "memory");
        }
        out[((size_t)m0 * TT + t) * HID + hcol] = h0;
        if (t + 1 < TT) {
            const size_t xo0 = (size_t)(t + 1) * BATCH * HID + xb0;
            xr0 = __ldg(&g_xg[xo0]);
            xz0 = __ldg(&g_xg[SL + xo0]);
            xn0 = __ldg(&g_xg[2 * SL + xo0]);
        }
        if (tid == 0) {
            unsigned v;
            do {
                asm volatile("ld.acquire.gpu.u32 %0, [%1];"
                             : "=r"(v) : "l"(&g_count) : "memory");
            } while (v < target);
        }
        __syncthreads();
    }
}

// ---------------------------------------------------------------------------
extern "C" void kernel_launch(void* const* d_in, const int* in_sizes, int n_in,
                              void* d_out, int out_size)
{
    const float* x     = (const float*)d_in[0];
    const float* W_i_r = (const float*)d_in[1];
    const float* b_i_r = (const float*)d_in[2];
    const float* W_h_r = (const float*)d_in[3];
    const float* b_h_r = (const float*)d_in[4];
    const float* W_i_z = (const float*)d_in[5];
    const float* b_i_z = (const float*)d_in[6];
    const float* W_h_z = (const float*)d_in[7];
    const float* b_h_z = (const float*)d_in[8];
    const float* W_i_n = (const float*)d_in[9];
    const float* b_i_n = (const float*)d_in[10];
    const float* W_h_n = (const float*)d_in[11];
    const float* b_h_n = (const float*)d_in[12];
    float* out = (float*)d_out;

    cudaFuncSetAttribute(recur_kernel, cudaFuncAttributeMaxDynamicSharedMemorySize,
                         RSMEM_BYTES);
    cudaFuncSetAttribute(igemm_f16_fused, cudaFuncAttributeMaxDynamicSharedMemorySize,
                         IGSM_BYTES);

    reset_kernel<<<(BATCH * HID + 255) / 256, 256>>>();

    convert_kernel<<<2048, 256>>>(x, W_i_r, W_i_z, W_i_n);

    dim3 ig(HID / 64, (BATCH * TT) / 128);
    igemm_f16_fused<<<ig, 256, IGSM_BYTES>>>(b_i_r, b_i_z, b_i_n);

    recur_kernel<<<RGRID, NTHR, RSMEM_BYTES>>>(W_h_r, W_h_z, W_h_n,
                                               b_h_r, b_h_z, b_h_n, out);
}

// round 15
// speedup vs baseline: 1.3305x; 1.3305x over previous
#include <cuda_runtime.h>
#include <cuda_fp16.h>
#include <math.h>
#include <stdint.h>

#define HID    1024
#define INP    512
#define BATCH  64
#define TT     512
#define RGRID  128
#define NTHR   256

// recurrence smem: shared (kq,cc) A regions + reduction buffer
#define AW_STR   72                         // halves per row (64 + 8 pad)
#define AREG_B   (32 * AW_STR * 2)          // one (kq,cc) region: 4608 B
#define A_TOT_B  (16 * AREG_B)              // 4 kq x 4 cc: 73728 B
#define RED_B    (8 * 6 * 128 * 4)          // 24576 B
#define RSMEM_BYTES (A_TOT_B + RED_B)

// igemm smem (fused 3-gate): xs[2][128*IG_STR] + ws[2][3][64*IG_STR] halves
#define IG_STR 40
#define IGS_X  (128 * IG_STR)
#define IGS_W  (64 * IG_STR)
#define IGSM_BYTES ((2 * IGS_X + 6 * IGS_W) * 2)

// Scratch (device globals — allocation-free contract)
__device__ float  g_xg[(size_t)3 * TT * BATCH * HID];  // [g][t][b][h] input projections
__device__ __half g_xh[(size_t)BATCH * TT * INP];      // fp16 copy of x
__device__ __half g_wih[3][HID * INP];                 // fp16 copies of W_i_{r,z,n}
__device__ __half g_h[BATCH * HID];                    // hidden state (fp16)
__device__ unsigned g_count;                           // global barrier counter

// ---------------------------------------------------------------------------
__device__ __forceinline__ void mma_f16(float c[4], uint32_t a0, uint32_t a1,
                                        uint32_t a2, uint32_t a3,
                                        uint32_t b0, uint32_t b1) {
    asm volatile(
        "mma.sync.aligned.m16n8k16.row.col.f32.f16.f16.f32 "
        "{%0,%1,%2,%3}, {%4,%5,%6,%7}, {%8,%9}, {%0,%1,%2,%3};\n"
        : "+f"(c[0]), "+f"(c[1]), "+f"(c[2]), "+f"(c[3])
        : "r"(a0), "r"(a1), "r"(a2), "r"(a3), "r"(b0), "r"(b1));
}

__device__ __forceinline__ void ldsm_x4(uint32_t& r0, uint32_t& r1,
                                        uint32_t& r2, uint32_t& r3, uint32_t addr) {
    asm volatile("ldmatrix.sync.aligned.m8n8.x4.shared.b16 {%0,%1,%2,%3}, [%4];"
                 : "=r"(r0), "=r"(r1), "=r"(r2), "=r"(r3) : "r"(addr));
}

__device__ __forceinline__ void cp16ca(void* dst, const void* src) {
    uint32_t d = (uint32_t)__cvta_generic_to_shared(dst);
    asm volatile("cp.async.ca.shared.global [%0], [%1], 16;\n" :: "r"(d), "l"(src));
}
__device__ __forceinline__ void cp16cg(void* dst, const void* src) {
    uint32_t d = (uint32_t)__cvta_generic_to_shared(dst);
    asm volatile("cp.async.cg.shared.global [%0], [%1], 16;\n" :: "r"(d), "l"(src));
}
__device__ __forceinline__ void cp_commit() { asm volatile("cp.async.commit_group;\n"); }

__device__ __forceinline__ float sigmoidf_fast(float x) {
    return 1.0f / (1.0f + __expf(-x));
}
__device__ __forceinline__ float tanhf_fast(float x) {
    return 2.0f / (1.0f + __expf(-2.0f * x)) - 1.0f;
}

// ---------------------------------------------------------------------------
__global__ void reset_kernel()
{
    int i = blockIdx.x * blockDim.x + threadIdx.x;
    if (i == 0) g_count = 0u;
    if (i < BATCH * HID) g_h[i] = __float2half(0.0f);
}

// ---------------------------------------------------------------------------
// Convert x and W_i_* to fp16 (one-time pre-pass).
__global__ __launch_bounds__(256) void convert_kernel(
    const float* __restrict__ x,
    const float* __restrict__ Wr, const float* __restrict__ Wz, const float* __restrict__ Wn)
{
    const size_t stride = (size_t)gridDim.x * blockDim.x;
    const size_t i0 = (size_t)blockIdx.x * blockDim.x + threadIdx.x;

    const size_t NX4 = (size_t)BATCH * TT * INP / 4;
    for (size_t j = i0; j < NX4; j += stride) {
        float4 v = ((const float4*)x)[j];
        ((__half2*)g_xh)[j * 2]     = __floats2half2_rn(v.x, v.y);
        ((__half2*)g_xh)[j * 2 + 1] = __floats2half2_rn(v.z, v.w);
    }
    const size_t NW4 = (size_t)HID * INP / 4;
    for (size_t j = i0; j < NW4; j += stride) {
        float4 a = ((const float4*)Wr)[j];
        float4 b = ((const float4*)Wz)[j];
        float4 c = ((const float4*)Wn)[j];
        ((__half2*)g_wih[0])[j * 2]     = __floats2half2_rn(a.x, a.y);
        ((__half2*)g_wih[0])[j * 2 + 1] = __floats2half2_rn(a.z, a.w);
        ((__half2*)g_wih[1])[j * 2]     = __floats2half2_rn(b.x, b.y);
        ((__half2*)g_wih[1])[j * 2 + 1] = __floats2half2_rn(b.z, b.w);
        ((__half2*)g_wih[2])[j * 2]     = __floats2half2_rn(c.x, c.y);
        ((__half2*)g_wih[2])[j * 2 + 1] = __floats2half2_rn(c.z, c.w);
    }
}

// ---------------------------------------------------------------------------
// Input projection GEMM, fused over the 3 gates (fp16 MMA m16n8k16) — R12.
__global__ __launch_bounds__(256) void igemm_f16_fused(
    const float* __restrict__ br, const float* __restrict__ bz, const float* __restrict__ bn)
{
    extern __shared__ __half igs[];
    __half* xs = igs;                  // [2][IGS_X]
    __half* ws = igs + 2 * IGS_X;      // [2][3][IGS_W]

    const int m0 = blockIdx.y * 128;
    const int n0 = blockIdx.x * 64;
    const int tid  = threadIdx.x;
    const int w    = tid >> 5;
    const int lane = tid & 31;
    const int ar   = lane >> 2;
    const int ac   = lane & 3;
    const int wm   = w >> 1;
    const int wn   = w & 1;

    float acc[3][2][4][4];
#pragma unroll
    for (int g = 0; g < 3; g++)
#pragma unroll
        for (int mt = 0; mt < 2; mt++)
#pragma unroll
            for (int nt = 0; nt < 4; nt++)
#pragma unroll
                for (int q = 0; q < 4; q++) acc[g][mt][nt][q] = 0.0f;

    auto load_chunk = [&](int c) {
        const int k0 = c * 32;
        __half* xd = xs + (c & 1) * IGS_X;
        {
            int i = tid;
            int r = i >> 2, q = i & 3;
            cp16ca(&xd[r * IG_STR + q * 8], &g_xh[(size_t)(m0 + r) * INP + k0 + q * 8]);
            i = tid + 256; r = i >> 2; q = i & 3;
            cp16ca(&xd[r * IG_STR + q * 8], &g_xh[(size_t)(m0 + r) * INP + k0 + q * 8]);
        }
        __half* wd = ws + (c & 1) * (3 * IGS_W);
#pragma unroll
        for (int rep = 0; rep < 3; rep++) {
            const int job = tid + rep * 256;
            const int g  = job >> 8;
            const int rr = (job & 255) >> 2;
            const int q  = job & 3;
            cp16ca(&wd[g * IGS_W + rr * IG_STR + q * 8],
                   &g_wih[g][(size_t)(n0 + rr) * INP + k0 + q * 8]);
        }
        cp_commit();
    };

    load_chunk(0);

    for (int c = 0; c < INP / 32; c++) {
        asm volatile("cp.async.wait_group 0;\n");
        __syncthreads();
        if (c + 1 < INP / 32) load_chunk(c + 1);

        const __half* xb = xs + (c & 1) * IGS_X;
        const __half* wb = ws + (c & 1) * (3 * IGS_W);
        const uint32_t xb_base = (uint32_t)__cvta_generic_to_shared(xb);
        const uint32_t rowoff_b = 2u * ((uint32_t)(lane & 15) * IG_STR + (uint32_t)(lane >> 4) * 8);

#pragma unroll
        for (int s2 = 0; s2 < 2; s2++) {
            uint32_t afr[2][4];
#pragma unroll
            for (int mt = 0; mt < 2; mt++) {
                const uint32_t addr = xb_base
                    + 2u * (uint32_t)((wm * 32 + mt * 16) * IG_STR + s2 * 16)
                    + rowoff_b;
                ldsm_x4(afr[mt][0], afr[mt][1], afr[mt][2], afr[mt][3], addr);
            }
#pragma unroll
            for (int g = 0; g < 3; g++) {
#pragma unroll
                for (int nt = 0; nt < 4; nt++) {
                    const __half* bp = &wb[g * IGS_W
                        + (wn * 32 + nt * 8 + ar) * IG_STR + s2 * 16 + 2 * ac];
                    const uint32_t b0 = *(const uint32_t*)bp;
                    const uint32_t b1 = *(const uint32_t*)(bp + 8);
#pragma unroll
                    for (int mt = 0; mt < 2; mt++)
                        mma_f16(acc[g][mt][nt], afr[mt][0], afr[mt][1], afr[mt][2], afr[mt][3],
                                b0, b1);
                }
            }
        }
        __syncthreads();
    }

#pragma unroll
    for (int g = 0; g < 3; g++) {
        const float* __restrict__ bias = (g == 0) ? br : ((g == 1) ? bz : bn);
#pragma unroll
        for (int mt = 0; mt < 2; mt++) {
#pragma unroll
            for (int nt = 0; nt < 4; nt++) {
                const int h   = n0 + wn * 32 + nt * 8 + ac * 2;
                const float bv0 = bias[h], bv1 = bias[h + 1];

                int row = m0 + wm * 32 + mt * 16 + ar;
                int b = row >> 9, t = row & (TT - 1);
                size_t base = (((size_t)g * TT + t) * BATCH + b) * HID + h;
                *(float2*)&g_xg[base] = make_float2(acc[g][mt][nt][0] + bv0,
                                                    acc[g][mt][nt][1] + bv1);

                row += 8;
                b = row >> 9; t = row & (TT - 1);
                base = (((size_t)g * TT + t) * BATCH + b) * HID + h;
                *(float2*)&g_xg[base] = make_float2(acc[g][mt][nt][2] + bv0,
                                                    acc[g][mt][nt][3] + bv1);
            }
        }
    }
}

// ---------------------------------------------------------------------------
// Persistent recurrence kernel — 128 blocks = 64 column-groups x 2 batch
// halves. Block (cg = bid>>1, bh = bid&1) owns h-cols [cg*16,+16) (48 gate
// rows, j = gate*16 + col) for batches [bh*32,+32), full K=1024: reads only
// 64 KB of h per step (8 MB/step chip-wide). Warps: nh = w>>2 (n-half: rows
// nh*24..+24) x kq = w&3 (k-quarter). A (kq,cc) regions shared by the two
// nh warps of a kq: each loads 16 of 32 rows, waits own cp groups, pairs via
// named bar.sync(kq+1, 64). W in 96 regs/thread. One global barrier/step.
__global__ __launch_bounds__(NTHR, 1) void recur_kernel(
    const float* __restrict__ Wr, const float* __restrict__ Wz, const float* __restrict__ Wn,
    const float* __restrict__ bhr, const float* __restrict__ bhz, const float* __restrict__ bhn,
    float* __restrict__ out)
{
    extern __shared__ char smc[];
    __half* As  = (__half*)smc;                 // [4 kq][4 cc][32 rows][AW_STR]
    float*  red = (float*)(smc + A_TOT_B);      // [8][6][128]

    const int tid  = threadIdx.x;
    const int bid  = blockIdx.x;
    const int w    = tid >> 5;
    const int lane = tid & 31;
    const int ar   = lane >> 2;
    const int ac   = lane & 3;

    const int cg  = bid >> 1;
    const int bh  = bid & 1;
    const int H0  = cg * 16;
    const int B0  = bh * 32;
    const int nh  = w >> 2;          // n-half (0..1): rows nh*24..+24
    const int kq  = w & 3;           // k-quarter (0..3)
    const int rot = bid & 3;         // chunk rotation

    // epilogue mapping: col ec (0..15), batches B0+m0 and B0+m0+16
    const int ec = tid & 15;
    const int m0 = tid >> 4;         // 0..15
    const int hcol = H0 + ec;
    const float bR = __ldg(&bhr[hcol]);
    const float bZ = __ldg(&bhz[hcol]);
    const float bN = __ldg(&bhn[hcol]);

    // per-gate reduction coordinates (j = g*16 + ec)
    int nh_g[3], nt_g[3], jr_g[3];
#pragma unroll
    for (int g = 0; g < 3; g++) {
        const int j = g * 16 + ec;
        nh_g[g] = (j >= 24) ? 1 : 0;
        const int loc = j - nh_g[g] * 24;
        nt_g[g] = loc >> 3;
        jr_g[g] = loc & 7;
    }
    // rem within a 128-slot tile for (ml = m0, jr): same for m0 and m0+16
    int rem_g[3];
#pragma unroll
    for (int g = 0; g < 3; g++)
        rem_g[g] = (m0 & 7) * 16 + (jr_g[g] >> 1) * 4 + (m0 >> 3) * 2 + (jr_g[g] & 1);

    // ---- W fragments into registers; slot cc holds k-range ((rot+cc)&3)*256 ----
    // row j = nh*24 + nt*8 + ar; gate = j>>4, col = j&15.
    uint32_t wreg[4][4][3][2];
#pragma unroll
    for (int cc = 0; cc < 4; cc++) {
        const int kbase = ((rot + cc) & 3) * 256;
#pragma unroll
        for (int s2 = 0; s2 < 4; s2++)
#pragma unroll
            for (int nt = 0; nt < 3; nt++) {
                const int j    = nh * 24 + nt * 8 + ar;
                const int gate = j >> 4;
                const int col  = j & 15;
                const float* __restrict__ Wp = (gate == 0) ? Wr : ((gate == 1) ? Wz : Wn);
                const float* rowp = &Wp[(size_t)(H0 + col) * HID];
#pragma unroll
                for (int q = 0; q < 2; q++) {
                    const int k = kbase + kq * 64 + s2 * 16 + q * 8 + 2 * ac;
                    float2 v = *(const float2*)&rowp[k];
                    __half2 h2 = __floats2half2_rn(v.x, v.y);
                    wreg[cc][s2][nt][q] = *(uint32_t*)&h2;
                }
            }
    }

    const uint32_t as_base = (uint32_t)__cvta_generic_to_shared(As);
    const uint32_t rowoff_b = 2u * ((uint32_t)(lane & 15) * AW_STR + (uint32_t)(lane >> 4) * 8);

    // per-warp load: 16 rows (nh half) x 64 k of region (kq, cc).
    // 4 rows per instruction (8 x 16B pieces per row), 4 iters.
    const int lrow = lane >> 3;      // 0..3
    const int lpc  = lane & 7;       // 0..7
    auto load_chunk = [&](int cc, int kbase) {
        __half* dst = As + ((size_t)kq * 4 + cc) * (32 * AW_STR);
        const int ksrc = kbase + kq * 64 + lpc * 8;
#pragma unroll
        for (int it = 0; it < 4; it++) {
            const int row = nh * 16 + it * 4 + lrow;     // 0..31 within region
            cp16cg(&dst[row * AW_STR + lpc * 8],
                   &g_h[(size_t)(B0 + row) * HID + ksrc]);
        }
        cp_commit();
    };

    const int kof[4] = { ((rot + 0) & 3) * 256, ((rot + 1) & 3) * 256,
                         ((rot + 2) & 3) * 256, ((rot + 3) & 3) * 256 };

    // epilogue x operands: prefetch t = 0
    const size_t SL = (size_t)TT * BATCH * HID;
    const size_t xb0 = (size_t)(B0 + m0) * HID + hcol;
    const size_t xb1 = xb0 + (size_t)16 * HID;
    float xr0 = __ldg(&g_xg[xb0]);
    float xz0 = __ldg(&g_xg[SL + xb0]);
    float xn0 = __ldg(&g_xg[2 * SL + xb0]);
    float xr1 = __ldg(&g_xg[xb1]);
    float xz1 = __ldg(&g_xg[SL + xb1]);
    float xn1 = __ldg(&g_xg[2 * SL + xb1]);
    float hv0 = 0.0f, hv1 = 0.0f;    // h(0) == 0

    unsigned phase = 0;

    for (int t = 0; t < TT; t++) {
        // issue this warp's 4 half-chunk loads (4 per-thread commit groups)
        load_chunk(0, kof[0]); load_chunk(1, kof[1]);
        load_chunk(2, kof[2]); load_chunk(3, kof[3]);

        float acc[2][3][4];
#pragma unroll
        for (int mt2 = 0; mt2 < 2; mt2++)
#pragma unroll
            for (int nt = 0; nt < 3; nt++)
#pragma unroll
                for (int q = 0; q < 4; q++) acc[mt2][nt][q] = 0.0f;

        // pair-autonomous compute: only named pair barriers, no block syncs
#pragma unroll
        for (int cc = 0; cc < 4; cc++) {
            if (cc == 0)      asm volatile("cp.async.wait_group 3;\n");
            else if (cc == 1) asm volatile("cp.async.wait_group 2;\n");
            else if (cc == 2) asm volatile("cp.async.wait_group 1;\n");
            else              asm volatile("cp.async.wait_group 0;\n");
            // pair barrier: both nh warps of this kq have loaded their halves
            asm volatile("bar.sync %0, 64;" :: "r"(kq + 1) : "memory");

            const uint32_t buf = as_base + ((uint32_t)kq * 4 + cc) * AREG_B;
#pragma unroll
            for (int s2 = 0; s2 < 4; s2++) {
                const uint32_t kb_b = 2u * (uint32_t)(s2 * 16);
#pragma unroll
                for (int mt2 = 0; mt2 < 2; mt2++) {
                    uint32_t a0, a1, a2, a3;
                    const uint32_t addr = buf + 2u * (uint32_t)(mt2 * 16 * AW_STR)
                                        + kb_b + rowoff_b;
                    ldsm_x4(a0, a1, a2, a3, addr);
#pragma unroll
                    for (int nt = 0; nt < 3; nt++)
                        mma_f16(acc[mt2][nt], a0, a1, a2, a3,
                                wreg[cc][s2][nt][0], wreg[cc][s2][nt][1]);
                }
            }
        }

        // ---- write per-warp partials ----
#pragma unroll
        for (int mt2 = 0; mt2 < 2; mt2++)
#pragma unroll
            for (int nt = 0; nt < 3; nt++) {
                const int tile = mt2 * 3 + nt;
                *(float4*)&red[((w * 6 + tile) * 128) + lane * 4] =
                    make_float4(acc[mt2][nt][0], acc[mt2][nt][1],
                                acc[mt2][nt][2], acc[mt2][nt][3]);
            }
        __syncthreads();

        // ---- fused reduction + gate epilogue (2 outputs per thread) ----
        float h0, h1;
        {
            float A0[3], A1[3];
#pragma unroll
            for (int g = 0; g < 3; g++) {
                const int wb0 = nh_g[g] * 4;            // warp group base
                const int t0  = 0 * 3 + nt_g[g];        // mt2 = 0 tile
                const int t1  = 1 * 3 + nt_g[g];        // mt2 = 1 tile
                float s0 = 0.0f, s1 = 0.0f;
#pragma unroll
                for (int k2 = 0; k2 < 4; k2++) {
                    s0 += red[(((wb0 + k2) * 6 + t0) * 128) + rem_g[g]];
                    s1 += red[(((wb0 + k2) * 6 + t1) * 128) + rem_g[g]];
                }
                A0[g] = s0; A1[g] = s1;
            }

            const float r0 = sigmoidf_fast(xr0 + A0[0] + bR);
            const float z0 = sigmoidf_fast(xz0 + A0[1] + bZ);
            const float n0 = tanhf_fast(xn0 + r0 * (A0[2] + bN));
            h0 = (1.0f - z0) * n0 + z0 * hv0;
            const __half h0h = __float2half(h0);
            g_h[(size_t)(B0 + m0) * HID + hcol] = h0h;
            hv0 = __half2float(h0h);

            const float r1 = sigmoidf_fast(xr1 + A1[0] + bR);
            const float z1 = sigmoidf_fast(xz1 + A1[1] + bZ);
            const float n1 = tanhf_fast(xn1 + r1 * (A1[2] + bN));
            h1 = (1.0f - z1) * n1 + z1 * hv1;
            const __half h1h = __float2half(h1);
            g_h[(size_t)(B0 + m0 + 16) * HID + hcol] = h1h;
            hv1 = __half2float(h1h);
        }

        // ---- barrier: arrive, then overlap out-stores + x(t+1) prefetch ----
        phase += 1;
        const unsigned target = phase * RGRID;
        __syncthreads();                  // all g_h stores issued block-wide
        if (tid == 0) {
            unsigned old;
            asm volatile("atom.add.release.gpu.u32 %0, [%1], 1;"
                         : "=r"(old) : "l"(&g_count) : "memory");
        }
        out[((size_t)(B0 + m0) * TT + t) * HID + hcol] = h0;
        out[((size_t)(B0 + m0 + 16) * TT + t) * HID + hcol] = h1;
        if (t + 1 < TT) {
            const size_t xo0 = (size_t)(t + 1) * BATCH * HID + xb0;
            const size_t xo1 = (size_t)(t + 1) * BATCH * HID + xb1;
            xr0 = __ldg(&g_xg[xo0]);
            xz0 = __ldg(&g_xg[SL + xo0]);
            xn0 = __ldg(&g_xg[2 * SL + xo0]);
            xr1 = __ldg(&g_xg[xo1]);
            xz1 = __ldg(&g_xg[SL + xo1]);
            xn1 = __ldg(&g_xg[2 * SL + xo1]);
        }
        if (tid == 0) {
            unsigned v;
            do {
                asm volatile("ld.acquire.gpu.u32 %0, [%1];"
                             : "=r"(v) : "l"(&g_count) : "memory");
            } while (v < target);
        }
        __syncthreads();
    }
}

// ---------------------------------------------------------------------------
extern "C" void kernel_launch(void* const* d_in, const int* in_sizes, int n_in,
                              void* d_out, int out_size)
{
    const float* x     = (const float*)d_in[0];
    const float* W_i_r = (const float*)d_in[1];
    const float* b_i_r = (const float*)d_in[2];
    const float* W_h_r = (const float*)d_in[3];
    const float* b_h_r = (const float*)d_in[4];
    const float* W_i_z = (const float*)d_in[5];
    const float* b_i_z = (const float*)d_in[6];
    const float* W_h_z = (const float*)d_in[7];
    const float* b_h_z = (const float*)d_in[8];
    const float* W_i_n = (const float*)d_in[9];
    const float* b_i_n = (const float*)d_in[10];
    const float* W_h_n = (const float*)d_in[11];
    const float* b_h_n = (const float*)d_in[12];
    float* out = (float*)d_out;

    cudaFuncSetAttribute(recur_kernel, cudaFuncAttributeMaxDynamicSharedMemorySize,
                         RSMEM_BYTES);
    cudaFuncSetAttribute(igemm_f16_fused, cudaFuncAttributeMaxDynamicSharedMemorySize,
                         IGSM_BYTES);

    reset_kernel<<<(BATCH * HID + 255) / 256, 256>>>();

    convert_kernel<<<2048, 256>>>(x, W_i_r, W_i_z, W_i_n);

    dim3 ig(HID / 64, (BATCH * TT) / 128);
    igemm_f16_fused<<<ig, 256, IGSM_BYTES>>>(b_i_r, b_i_z, b_i_n);

    recur_kernel<<<RGRID, NTHR, RSMEM_BYTES>>>(W_h_r, W_h_z, W_h_n,
                                               b_h_r, b_h_z, b_h_n, out);
}